// round 6
// baseline (speedup 1.0000x reference)
#include <cuda_runtime.h>
#include <math.h>
#include <float.h>

#define MAX_NODES 100000
#define MAX_EDGES 1600000

// Scratch — referenced directly from device code (no host-side symbol APIs).
__device__ __align__(16) float g_bufA[MAX_NODES * 64];
__device__ __align__(16) float g_bufB[MAX_NODES * 64];
__device__ int   g_deg_out[MAX_NODES];
__device__ int   g_deg_in[MAX_NODES];
__device__ int   g_rowptr[MAX_NODES + 1];
__device__ int   g_cursor[MAX_NODES];
__device__ int   g_col[MAX_EDGES];
__device__ float g_ns[MAX_NODES];
__device__ float g_nd[MAX_NODES];

// ---------------------------------------------------------------------------
__global__ void zero_deg_kernel(int n) {
    int i = blockIdx.x * blockDim.x + threadIdx.x;
    if (i < n) { g_deg_out[i] = 0; g_deg_in[i] = 0; }
}

// NOTE: src/dst are int32 on device (JAX default x64-disabled coerces the
// reference's jnp.int64 to int32). Reading them as long long was the 717 trap.
__global__ void deg_kernel(const int* __restrict__ src,
                           const int* __restrict__ dst, int E) {
    int i = blockIdx.x * blockDim.x + threadIdx.x;
    if (i < E) {
        atomicAdd(&g_deg_out[src[i]], 1);
        atomicAdd(&g_deg_in[dst[i]], 1);
    }
}

__global__ void norm_kernel(int n) {
    int i = blockIdx.x * blockDim.x + threadIdx.x;
    if (i < n) {
        int a = g_deg_out[i];
        int b = g_deg_in[i];
        g_ns[i] = (a > 0) ? rsqrtf((float)a) : 0.0f;
        g_nd[i] = (b > 0) ? rsqrtf((float)b) : 0.0f;
    }
}

// Single-block exclusive scan of g_deg_in -> g_rowptr (+ g_cursor copy).
__global__ void scan_kernel(int n) {
    __shared__ int ssum[1024];
    int tid = threadIdx.x;
    int chunk = (n + 1023) / 1024;
    int lo = tid * chunk;
    int hi = min(lo + chunk, n);
    int s = 0;
    for (int i = lo; i < hi; i++) s += g_deg_in[i];
    ssum[tid] = s;
    __syncthreads();
    for (int off = 1; off < 1024; off <<= 1) {
        int v = (tid >= off) ? ssum[tid - off] : 0;
        __syncthreads();
        ssum[tid] += v;
        __syncthreads();
    }
    int base = (tid > 0) ? ssum[tid - 1] : 0;
    for (int i = lo; i < hi; i++) {
        g_rowptr[i] = base;
        g_cursor[i] = base;
        base += g_deg_in[i];
    }
    if (tid == 1023) g_rowptr[n] = ssum[1023];
}

__global__ void fill_kernel(const int* __restrict__ src,
                            const int* __restrict__ dst, int E) {
    int e = blockIdx.x * blockDim.x + threadIdx.x;
    if (e < E) {
        int d = dst[e];
        int pos = atomicAdd(&g_cursor[d], 1);
        g_col[pos] = src[e];
    }
}

// ---------------------------------------------------------------------------
// GEMM: g_bufA[M,N] = (X[M,K] @ W[K,N]) * g_ns[row]
// X = Xext if non-null else g_bufB. Ws padded to K*64 (zero-filled) so the
// float4 B-loads are always in bounds for N=40.
// ---------------------------------------------------------------------------
template<int K, int N>
__global__ void gemm_ns_kernel(const float* __restrict__ Xext,
                               const float* __restrict__ W, int M) {
    __shared__ float Ws[K * 64];
    __shared__ float As[64 * 33];

    const float* X = Xext ? Xext : g_bufB;
    const int tid = threadIdx.x;
    const int tr = tid >> 4;
    const int tc = tid & 15;
    const int row0 = blockIdx.x * 64;

    for (int t = tid; t < K * 64; t += 256) {
        int k = t >> 6, c = t & 63;
        Ws[t] = (c < N) ? W[k * N + c] : 0.0f;
    }

    float acc[4][4];
#pragma unroll
    for (int i = 0; i < 4; i++)
#pragma unroll
        for (int j = 0; j < 4; j++) acc[i][j] = 0.0f;

    for (int k0 = 0; k0 < K; k0 += 32) {
        for (int t = tid; t < 64 * 32; t += 256) {
            int r = t >> 5, c = t & 31;
            int row = row0 + r;
            As[r * 33 + c] = (row < M) ? X[(long long)row * K + k0 + c] : 0.0f;
        }
        __syncthreads();
#pragma unroll
        for (int kk = 0; kk < 32; kk++) {
            float a[4];
#pragma unroll
            for (int i = 0; i < 4; i++) a[i] = As[(tr * 4 + i) * 33 + kk];
            float4 b = *reinterpret_cast<const float4*>(&Ws[(k0 + kk) * 64 + tc * 4]);
#pragma unroll
            for (int i = 0; i < 4; i++) {
                acc[i][0] += a[i] * b.x;
                acc[i][1] += a[i] * b.y;
                acc[i][2] += a[i] * b.z;
                acc[i][3] += a[i] * b.w;
            }
        }
        __syncthreads();
    }

#pragma unroll
    for (int i = 0; i < 4; i++) {
        int row = row0 + tr * 4 + i;
        if (row < M) {
            float s = g_ns[row];
#pragma unroll
            for (int j = 0; j < 4; j++) {
                int col = tc * 4 + j;
                if (col < N) g_bufA[(long long)row * N + col] = acc[i][j] * s;
            }
        }
    }
}

// ---------------------------------------------------------------------------
// Fused SpMM-gather (from g_bufA via CSR) + nd + bias + [relu] + log_softmax.
// Warp per dst row. out = outp if non-null else g_bufB. No float atomics.
// ---------------------------------------------------------------------------
template<int F, bool RELU>
__global__ void spmm_fused_kernel(const float* __restrict__ bias, int n,
                                  float* __restrict__ outp) {
    constexpr int CH = F / 4;       // float4 chunks per row
    constexpr int G = 32 / CH;      // edge groups per warp

    int row = blockIdx.x * (blockDim.x >> 5) + (threadIdx.x >> 5);
    if (row >= n) return;
    int lane = threadIdx.x & 31;
    int g = lane / CH;
    int sub = lane - g * CH;

    int start = g_rowptr[row];
    int end = g_rowptr[row + 1];

    float4 acc = make_float4(0.f, 0.f, 0.f, 0.f);
    if (g < G) {
        for (int e = start + g; e < end; e += G) {
            int s = g_col[e];
            float4 v = *reinterpret_cast<const float4*>(&g_bufA[(long long)s * F + sub * 4]);
            acc.x += v.x; acc.y += v.y; acc.z += v.z; acc.w += v.w;
        }
    }

    float4 tot = acc;
#pragma unroll
    for (int k = 1; k < G; k++) {
        tot.x += __shfl_sync(0xffffffffu, acc.x, sub + k * CH);
        tot.y += __shfl_sync(0xffffffffu, acc.y, sub + k * CH);
        tot.z += __shfl_sync(0xffffffffu, acc.z, sub + k * CH);
        tot.w += __shfl_sync(0xffffffffu, acc.w, sub + k * CH);
    }

    float ndv = g_nd[row];
    float4 bv = *reinterpret_cast<const float4*>(bias + sub * 4);
    float4 x;
    x.x = tot.x * ndv + bv.x;
    x.y = tot.y * ndv + bv.y;
    x.z = tot.z * ndv + bv.z;
    x.w = tot.w * ndv + bv.w;
    if (RELU) {
        x.x = fmaxf(x.x, 0.f); x.y = fmaxf(x.y, 0.f);
        x.z = fmaxf(x.z, 0.f); x.w = fmaxf(x.w, 0.f);
    }

    bool valid = (lane < CH);
    float m = valid ? fmaxf(fmaxf(x.x, x.y), fmaxf(x.z, x.w)) : -FLT_MAX;
#pragma unroll
    for (int o = 8; o > 0; o >>= 1) m = fmaxf(m, __shfl_xor_sync(0xffffffffu, m, o));
    float s = valid ? (expf(x.x - m) + expf(x.y - m) + expf(x.z - m) + expf(x.w - m)) : 0.f;
#pragma unroll
    for (int o = 8; o > 0; o >>= 1) s += __shfl_xor_sync(0xffffffffu, s, o);
    float ls = m + logf(s);

    if (valid) {
        float* out = outp ? outp : g_bufB;
        float4 r;
        r.x = x.x - ls; r.y = x.y - ls; r.z = x.z - ls; r.w = x.w - ls;
        *reinterpret_cast<float4*>(out + (long long)row * F + sub * 4) = r;
    }
}

// ---------------------------------------------------------------------------
// Launch — kernel launches only.
// ---------------------------------------------------------------------------
extern "C" void kernel_launch(void* const* d_in, const int* in_sizes, int n_in,
                              void* d_out, int out_size) {
    const float* feats = (const float*)d_in[0];
    const int*   src   = (const int*)d_in[1];   // int32 (JAX x64 disabled)
    const int*   dst   = (const int*)d_in[2];   // int32
    const float* W0    = (const float*)d_in[3];
    const float* b0    = (const float*)d_in[4];
    const float* W1    = (const float*)d_in[5];
    const float* b1    = (const float*)d_in[6];
    const float* W2    = (const float*)d_in[7];
    const float* b2    = (const float*)d_in[8];

    int N = in_sizes[0] / 128;   // 100000
    int E = in_sizes[1];         // 1600000
    float* outp = (float*)d_out;

    // ---- CSR build + norms ----
    zero_deg_kernel<<<(N + 255) / 256, 256>>>(N);
    deg_kernel<<<(E + 255) / 256, 256>>>(src, dst, E);
    norm_kernel<<<(N + 255) / 256, 256>>>(N);
    scan_kernel<<<1, 1024>>>(N);
    fill_kernel<<<(E + 255) / 256, 256>>>(src, dst, E);

    int spmm_blocks = (N + 7) / 8;   // 8 warps (rows) per 256-thread block
    int gemm_blocks = (N + 63) / 64;

    // ---- layer 0: 128 -> 64, relu, log_softmax ----
    gemm_ns_kernel<128, 64><<<gemm_blocks, 256>>>(feats, W0, N);
    spmm_fused_kernel<64, true><<<spmm_blocks, 256>>>(b0, N, nullptr);

    // ---- layer 1: 64 -> 64, relu, log_softmax ----
    gemm_ns_kernel<64, 64><<<gemm_blocks, 256>>>(nullptr, W1, N);
    spmm_fused_kernel<64, true><<<spmm_blocks, 256>>>(b1, N, nullptr);

    // ---- layer 2: 64 -> 40, no relu, log_softmax -> d_out ----
    gemm_ns_kernel<64, 40><<<gemm_blocks, 256>>>(nullptr, W2, N);
    spmm_fused_kernel<40, false><<<spmm_blocks, 256>>>(b2, N, outp);
}

// round 7
// speedup vs baseline: 1.5434x; 1.5434x over previous
#include <cuda_runtime.h>
#include <math.h>
#include <float.h>

#define MAX_NODES 100000
#define MAX_EDGES 1600000
#define SCAN_TILE 1024
#define MAX_SCAN_BLOCKS 128   // ceil(100000/1024)=98 <= 128

// Scratch — referenced directly from device code (no host-side symbol APIs).
__device__ __align__(16) float g_bufA[MAX_NODES * 64];
__device__ __align__(16) float g_bufB[MAX_NODES * 64];
__device__ int   g_deg_out[MAX_NODES];
__device__ __align__(16) int g_deg_in[MAX_NODES];
__device__ int   g_rowptr[MAX_NODES + 1];
__device__ int   g_cursor[MAX_NODES];
__device__ int   g_col[MAX_EDGES];
__device__ float g_ns[MAX_NODES];
__device__ float g_nd[MAX_NODES];
__device__ int   g_blksum[MAX_SCAN_BLOCKS];
__device__ int   g_blkoff[MAX_SCAN_BLOCKS];

// ---------------------------------------------------------------------------
__global__ void zero_deg_kernel(int n) {
    int i = blockIdx.x * blockDim.x + threadIdx.x;
    if (i < n) { g_deg_out[i] = 0; g_deg_in[i] = 0; }
}

// src/dst are int32 on device (JAX x64 disabled).
__global__ void deg_kernel(const int* __restrict__ src,
                           const int* __restrict__ dst, int E) {
    int i = blockIdx.x * blockDim.x + threadIdx.x;
    if (i < E) {
        atomicAdd(&g_deg_out[src[i]], 1);
        atomicAdd(&g_deg_in[dst[i]], 1);
    }
}

__global__ void norm_kernel(int n) {
    int i = blockIdx.x * blockDim.x + threadIdx.x;
    if (i < n) {
        int a = g_deg_out[i];
        int b = g_deg_in[i];
        g_ns[i] = (a > 0) ? rsqrtf((float)a) : 0.0f;
        g_nd[i] = (b > 0) ? rsqrtf((float)b) : 0.0f;
    }
}

// ---------------------------------------------------------------------------
// Grid-wide exclusive scan of g_deg_in -> g_rowptr/g_cursor (3 kernels).
// ---------------------------------------------------------------------------
__device__ __forceinline__ int warp_incl_scan(int v, int lane) {
#pragma unroll
    for (int o = 1; o < 32; o <<= 1) {
        int t = __shfl_up_sync(0xffffffffu, v, o);
        if (lane >= o) v += t;
    }
    return v;
}

// Stage 1: per-block (1024-element tile) sum. 256 threads x int4.
__global__ void scan_reduce_kernel(int n) {
    __shared__ int wsum[8];
    int tid = threadIdx.x, lane = tid & 31, wid = tid >> 5;
    int base = blockIdx.x * SCAN_TILE + tid * 4;
    int s = 0;
    if (base < n) {   // n % 4 == 0, so full int4 is safe when base < n
        int4 v = *reinterpret_cast<const int4*>(&g_deg_in[base]);
        s = v.x + v.y + v.z + v.w;
    }
#pragma unroll
    for (int o = 16; o > 0; o >>= 1) s += __shfl_xor_sync(0xffffffffu, s, o);
    if (lane == 0) wsum[wid] = s;
    __syncthreads();
    if (tid == 0) {
        int t = 0;
#pragma unroll
        for (int w = 0; w < 8; w++) t += wsum[w];
        g_blksum[blockIdx.x] = t;
    }
}

// Stage 2: single small block scans the block sums (nb <= 128) -> exclusive offsets.
__global__ void scan_blksums_kernel(int nb, int n) {
    __shared__ int woff[4];
    int tid = threadIdx.x, lane = tid & 31, wid = tid >> 5;  // 128 threads
    int v = (tid < nb) ? g_blksum[tid] : 0;
    int incl = warp_incl_scan(v, lane);
    if (lane == 31) woff[wid] = incl;
    __syncthreads();
    if (tid == 0) {
        int acc = 0;
#pragma unroll
        for (int w = 0; w < 4; w++) { int t = woff[w]; woff[w] = acc; acc += t; }
    }
    __syncthreads();
    int excl = incl - v + woff[wid];
    if (tid < nb) g_blkoff[tid] = excl;
    if (tid == nb - 1) g_rowptr[n] = excl + v;   // total edge count
}

// Stage 3: per-block exclusive scan within each 1024 tile + block offset.
__global__ void scan_write_kernel(int n) {
    __shared__ int woff[8];
    int tid = threadIdx.x, lane = tid & 31, wid = tid >> 5;  // 256 threads
    int base = blockIdx.x * SCAN_TILE + tid * 4;
    int4 v = make_int4(0, 0, 0, 0);
    if (base < n) v = *reinterpret_cast<const int4*>(&g_deg_in[base]);
    int s = v.x + v.y + v.z + v.w;
    int incl = warp_incl_scan(s, lane);
    if (lane == 31) woff[wid] = incl;
    __syncthreads();
    if (tid == 0) {
        int acc = 0;
#pragma unroll
        for (int w = 0; w < 8; w++) { int t = woff[w]; woff[w] = acc; acc += t; }
    }
    __syncthreads();
    if (base < n) {
        int excl = incl - s + woff[wid] + g_blkoff[blockIdx.x];
        int p0 = excl, p1 = p0 + v.x, p2 = p1 + v.y, p3 = p2 + v.z;
        *reinterpret_cast<int4*>(&g_rowptr[base]) = make_int4(p0, p1, p2, p3);
        *reinterpret_cast<int4*>(&g_cursor[base]) = make_int4(p0, p1, p2, p3);
    }
}

__global__ void fill_kernel(const int* __restrict__ src,
                            const int* __restrict__ dst, int E) {
    int e = blockIdx.x * blockDim.x + threadIdx.x;
    if (e < E) {
        int d = dst[e];
        int pos = atomicAdd(&g_cursor[d], 1);
        g_col[pos] = src[e];
    }
}

// ---------------------------------------------------------------------------
// GEMM: g_bufA[M,N] = (X[M,K] @ W[K,N]) * g_ns[row]
// X = Xext if non-null else g_bufB. Ws padded to K*64 (zero-filled).
// ---------------------------------------------------------------------------
template<int K, int N>
__global__ void gemm_ns_kernel(const float* __restrict__ Xext,
                               const float* __restrict__ W, int M) {
    __shared__ float Ws[K * 64];
    __shared__ float As[64 * 33];

    const float* X = Xext ? Xext : g_bufB;
    const int tid = threadIdx.x;
    const int tr = tid >> 4;
    const int tc = tid & 15;
    const int row0 = blockIdx.x * 64;

    for (int t = tid; t < K * 64; t += 256) {
        int k = t >> 6, c = t & 63;
        Ws[t] = (c < N) ? W[k * N + c] : 0.0f;
    }

    float acc[4][4];
#pragma unroll
    for (int i = 0; i < 4; i++)
#pragma unroll
        for (int j = 0; j < 4; j++) acc[i][j] = 0.0f;

    for (int k0 = 0; k0 < K; k0 += 32) {
        for (int t = tid; t < 64 * 32; t += 256) {
            int r = t >> 5, c = t & 31;
            int row = row0 + r;
            As[r * 33 + c] = (row < M) ? X[(long long)row * K + k0 + c] : 0.0f;
        }
        __syncthreads();
#pragma unroll
        for (int kk = 0; kk < 32; kk++) {
            float a[4];
#pragma unroll
            for (int i = 0; i < 4; i++) a[i] = As[(tr * 4 + i) * 33 + kk];
            float4 b = *reinterpret_cast<const float4*>(&Ws[(k0 + kk) * 64 + tc * 4]);
#pragma unroll
            for (int i = 0; i < 4; i++) {
                acc[i][0] += a[i] * b.x;
                acc[i][1] += a[i] * b.y;
                acc[i][2] += a[i] * b.z;
                acc[i][3] += a[i] * b.w;
            }
        }
        __syncthreads();
    }

#pragma unroll
    for (int i = 0; i < 4; i++) {
        int row = row0 + tr * 4 + i;
        if (row < M) {
            float s = g_ns[row];
#pragma unroll
            for (int j = 0; j < 4; j++) {
                int col = tc * 4 + j;
                if (col < N) g_bufA[(long long)row * N + col] = acc[i][j] * s;
            }
        }
    }
}

// ---------------------------------------------------------------------------
// Fused SpMM-gather (from g_bufA via CSR) + nd + bias + [relu] + log_softmax.
// Warp per dst row. out = outp if non-null else g_bufB. No float atomics.
// ---------------------------------------------------------------------------
template<int F, bool RELU>
__global__ void spmm_fused_kernel(const float* __restrict__ bias, int n,
                                  float* __restrict__ outp) {
    constexpr int CH = F / 4;       // float4 chunks per row
    constexpr int G = 32 / CH;      // edge groups per warp

    int row = blockIdx.x * (blockDim.x >> 5) + (threadIdx.x >> 5);
    if (row >= n) return;
    int lane = threadIdx.x & 31;
    int g = lane / CH;
    int sub = lane - g * CH;

    int start = g_rowptr[row];
    int end = g_rowptr[row + 1];

    float4 acc = make_float4(0.f, 0.f, 0.f, 0.f);
    if (g < G) {
        for (int e = start + g; e < end; e += G) {
            int s = g_col[e];
            float4 v = *reinterpret_cast<const float4*>(&g_bufA[(long long)s * F + sub * 4]);
            acc.x += v.x; acc.y += v.y; acc.z += v.z; acc.w += v.w;
        }
    }

    float4 tot = acc;
#pragma unroll
    for (int k = 1; k < G; k++) {
        tot.x += __shfl_sync(0xffffffffu, acc.x, sub + k * CH);
        tot.y += __shfl_sync(0xffffffffu, acc.y, sub + k * CH);
        tot.z += __shfl_sync(0xffffffffu, acc.z, sub + k * CH);
        tot.w += __shfl_sync(0xffffffffu, acc.w, sub + k * CH);
    }

    float ndv = g_nd[row];
    float4 bv = *reinterpret_cast<const float4*>(bias + sub * 4);
    float4 x;
    x.x = tot.x * ndv + bv.x;
    x.y = tot.y * ndv + bv.y;
    x.z = tot.z * ndv + bv.z;
    x.w = tot.w * ndv + bv.w;
    if (RELU) {
        x.x = fmaxf(x.x, 0.f); x.y = fmaxf(x.y, 0.f);
        x.z = fmaxf(x.z, 0.f); x.w = fmaxf(x.w, 0.f);
    }

    bool valid = (lane < CH);
    float m = valid ? fmaxf(fmaxf(x.x, x.y), fmaxf(x.z, x.w)) : -FLT_MAX;
#pragma unroll
    for (int o = 8; o > 0; o >>= 1) m = fmaxf(m, __shfl_xor_sync(0xffffffffu, m, o));
    float s = valid ? (expf(x.x - m) + expf(x.y - m) + expf(x.z - m) + expf(x.w - m)) : 0.f;
#pragma unroll
    for (int o = 8; o > 0; o >>= 1) s += __shfl_xor_sync(0xffffffffu, s, o);
    float ls = m + logf(s);

    if (valid) {
        float* out = outp ? outp : g_bufB;
        float4 r;
        r.x = x.x - ls; r.y = x.y - ls; r.z = x.z - ls; r.w = x.w - ls;
        *reinterpret_cast<float4*>(out + (long long)row * F + sub * 4) = r;
    }
}

// ---------------------------------------------------------------------------
// Launch — kernel launches only.
// ---------------------------------------------------------------------------
extern "C" void kernel_launch(void* const* d_in, const int* in_sizes, int n_in,
                              void* d_out, int out_size) {
    const float* feats = (const float*)d_in[0];
    const int*   src   = (const int*)d_in[1];   // int32
    const int*   dst   = (const int*)d_in[2];   // int32
    const float* W0    = (const float*)d_in[3];
    const float* b0    = (const float*)d_in[4];
    const float* W1    = (const float*)d_in[5];
    const float* b1    = (const float*)d_in[6];
    const float* W2    = (const float*)d_in[7];
    const float* b2    = (const float*)d_in[8];

    int N = in_sizes[0] / 128;   // 100000
    int E = in_sizes[1];         // 1600000
    float* outp = (float*)d_out;

    int scan_blocks = (N + SCAN_TILE - 1) / SCAN_TILE;   // 98

    // ---- CSR build + norms ----
    zero_deg_kernel<<<(N + 255) / 256, 256>>>(N);
    deg_kernel<<<(E + 255) / 256, 256>>>(src, dst, E);
    norm_kernel<<<(N + 255) / 256, 256>>>(N);
    scan_reduce_kernel<<<scan_blocks, 256>>>(N);
    scan_blksums_kernel<<<1, 128>>>(scan_blocks, N);
    scan_write_kernel<<<scan_blocks, 256>>>(N);
    fill_kernel<<<(E + 255) / 256, 256>>>(src, dst, E);

    int spmm_blocks = (N + 7) / 8;   // 8 warps (rows) per 256-thread block
    int gemm_blocks = (N + 63) / 64;

    // ---- layer 0: 128 -> 64, relu, log_softmax ----
    gemm_ns_kernel<128, 64><<<gemm_blocks, 256>>>(feats, W0, N);
    spmm_fused_kernel<64, true><<<spmm_blocks, 256>>>(b0, N, nullptr);

    // ---- layer 1: 64 -> 64, relu, log_softmax ----
    gemm_ns_kernel<64, 64><<<gemm_blocks, 256>>>(nullptr, W1, N);
    spmm_fused_kernel<64, true><<<spmm_blocks, 256>>>(b1, N, nullptr);

    // ---- layer 2: 64 -> 40, no relu, log_softmax -> d_out ----
    gemm_ns_kernel<64, 40><<<gemm_blocks, 256>>>(nullptr, W2, N);
    spmm_fused_kernel<40, false><<<spmm_blocks, 256>>>(b2, N, outp);
}

// round 8
// speedup vs baseline: 1.6155x; 1.0467x over previous
#include <cuda_runtime.h>
#include <math.h>
#include <float.h>

#define MAX_NODES 100000
#define MAX_EDGES 1600000
#define SCAN_TILE 1024
#define MAX_SCAN_BLOCKS 128   // ceil(100000/1024)=98 <= 128

// Scratch — referenced directly from device code.
__device__ __align__(16) float g_bufA[MAX_NODES * 64];
__device__ __align__(16) float g_bufB[MAX_NODES * 64];
__device__ int   g_deg_out[MAX_NODES];
__device__ __align__(16) int g_deg_in[MAX_NODES];
__device__ int   g_rowptr[MAX_NODES + 1];
__device__ int   g_cursor[MAX_NODES];
__device__ int   g_col[MAX_EDGES];
__device__ float g_ns[MAX_NODES];
__device__ float g_nd[MAX_NODES];
__device__ int   g_blksum[MAX_SCAN_BLOCKS];
__device__ int   g_blkoff[MAX_SCAN_BLOCKS];

// ---------------------------------------------------------------------------
__global__ void zero_deg_kernel(int n) {
    int i = blockIdx.x * blockDim.x + threadIdx.x;
    if (i < n) { g_deg_out[i] = 0; g_deg_in[i] = 0; }
}

// src/dst are int32 on device (JAX x64 disabled).
__global__ void deg_kernel(const int* __restrict__ src,
                           const int* __restrict__ dst, int E) {
    int i = blockIdx.x * blockDim.x + threadIdx.x;
    if (i < E) {
        atomicAdd(&g_deg_out[src[i]], 1);
        atomicAdd(&g_deg_in[dst[i]], 1);
    }
}

__global__ void norm_kernel(int n) {
    int i = blockIdx.x * blockDim.x + threadIdx.x;
    if (i < n) {
        int a = g_deg_out[i];
        int b = g_deg_in[i];
        g_ns[i] = (a > 0) ? rsqrtf((float)a) : 0.0f;
        g_nd[i] = (b > 0) ? rsqrtf((float)b) : 0.0f;
    }
}

// ---------------------------------------------------------------------------
// Grid-wide exclusive scan of g_deg_in -> g_rowptr/g_cursor (3 kernels).
// ---------------------------------------------------------------------------
__device__ __forceinline__ int warp_incl_scan(int v, int lane) {
#pragma unroll
    for (int o = 1; o < 32; o <<= 1) {
        int t = __shfl_up_sync(0xffffffffu, v, o);
        if (lane >= o) v += t;
    }
    return v;
}

__global__ void scan_reduce_kernel(int n) {
    __shared__ int wsum[8];
    int tid = threadIdx.x, lane = tid & 31, wid = tid >> 5;
    int base = blockIdx.x * SCAN_TILE + tid * 4;
    int s = 0;
    if (base < n) {
        int4 v = *reinterpret_cast<const int4*>(&g_deg_in[base]);
        s = v.x + v.y + v.z + v.w;
    }
#pragma unroll
    for (int o = 16; o > 0; o >>= 1) s += __shfl_xor_sync(0xffffffffu, s, o);
    if (lane == 0) wsum[wid] = s;
    __syncthreads();
    if (tid == 0) {
        int t = 0;
#pragma unroll
        for (int w = 0; w < 8; w++) t += wsum[w];
        g_blksum[blockIdx.x] = t;
    }
}

__global__ void scan_blksums_kernel(int nb, int n) {
    __shared__ int woff[4];
    int tid = threadIdx.x, lane = tid & 31, wid = tid >> 5;  // 128 threads
    int v = (tid < nb) ? g_blksum[tid] : 0;
    int incl = warp_incl_scan(v, lane);
    if (lane == 31) woff[wid] = incl;
    __syncthreads();
    if (tid == 0) {
        int acc = 0;
#pragma unroll
        for (int w = 0; w < 4; w++) { int t = woff[w]; woff[w] = acc; acc += t; }
    }
    __syncthreads();
    int excl = incl - v + woff[wid];
    if (tid < nb) g_blkoff[tid] = excl;
    if (tid == nb - 1) g_rowptr[n] = excl + v;
}

__global__ void scan_write_kernel(int n) {
    __shared__ int woff[8];
    int tid = threadIdx.x, lane = tid & 31, wid = tid >> 5;  // 256 threads
    int base = blockIdx.x * SCAN_TILE + tid * 4;
    int4 v = make_int4(0, 0, 0, 0);
    if (base < n) v = *reinterpret_cast<const int4*>(&g_deg_in[base]);
    int s = v.x + v.y + v.z + v.w;
    int incl = warp_incl_scan(s, lane);
    if (lane == 31) woff[wid] = incl;
    __syncthreads();
    if (tid == 0) {
        int acc = 0;
#pragma unroll
        for (int w = 0; w < 8; w++) { int t = woff[w]; woff[w] = acc; acc += t; }
    }
    __syncthreads();
    if (base < n) {
        int excl = incl - s + woff[wid] + g_blkoff[blockIdx.x];
        int p0 = excl, p1 = p0 + v.x, p2 = p1 + v.y, p3 = p2 + v.z;
        *reinterpret_cast<int4*>(&g_rowptr[base]) = make_int4(p0, p1, p2, p3);
        *reinterpret_cast<int4*>(&g_cursor[base]) = make_int4(p0, p1, p2, p3);
    }
}

__global__ void fill_kernel(const int* __restrict__ src,
                            const int* __restrict__ dst, int E) {
    int e = blockIdx.x * blockDim.x + threadIdx.x;
    if (e < E) {
        int d = dst[e];
        int pos = atomicAdd(&g_cursor[d], 1);
        g_col[pos] = src[e];
    }
}

// ---------------------------------------------------------------------------
// GEMM (packed f32x2): g_bufA[M,N] = (X[M,K] @ W[K,N]) * g_ns[row]
// A tile stored k-major (stride 68, 16B aligned) so LDS.128 yields 4 row
// values = 2 f32x2 pairs. Inner loop: 2 LDS.128 + 4 mov.b64 + 8 fma.rn.f32x2
// for 16 lane-FMAs (FFMA2 halves the rt=2 FFMA issue cost).
// ---------------------------------------------------------------------------
#define AS_S 68   // stride: 68*4B = 272 = 16*17 -> float4-aligned per kk row

template<int K, int N>
__global__ void gemm_ns_kernel(const float* __restrict__ Xext,
                               const float* __restrict__ W, int M) {
    __shared__ __align__(16) float Ws[K * 64];
    __shared__ __align__(16) float As[32 * AS_S];

    const float* X = Xext ? Xext : g_bufB;
    const int tid = threadIdx.x;
    const int tr = tid >> 4;   // 0..15 -> rows tr*4..tr*4+3
    const int tc = tid & 15;   // 0..15 -> cols tc*4..tc*4+3
    const int row0 = blockIdx.x * 64;

    for (int t = tid; t < K * 64; t += 256) {
        int k = t >> 6, c = t & 63;
        Ws[t] = (c < N) ? W[k * N + c] : 0.0f;
    }

    unsigned long long acc[2][4];
#pragma unroll
    for (int rp = 0; rp < 2; rp++)
#pragma unroll
        for (int c = 0; c < 4; c++) acc[rp][c] = 0ull;

    for (int k0 = 0; k0 < K; k0 += 32) {
        __syncthreads();   // protect As reuse across k0 tiles
        // Load 64 rows x 32 k, store transposed k-major: As[kk*AS_S + row]
#pragma unroll
        for (int it = 0; it < 2; it++) {
            int idx = tid + it * 256;          // 0..511
            int row = idx >> 3;                // 0..63
            int kc = idx & 7;                  // 0..7 (float4 chunk)
            float4 v = make_float4(0.f, 0.f, 0.f, 0.f);
            if (row0 + row < M)
                v = *reinterpret_cast<const float4*>(&X[(long long)(row0 + row) * K + k0 + kc * 4]);
            As[(kc * 4 + 0) * AS_S + row] = v.x;
            As[(kc * 4 + 1) * AS_S + row] = v.y;
            As[(kc * 4 + 2) * AS_S + row] = v.z;
            As[(kc * 4 + 3) * AS_S + row] = v.w;
        }
        __syncthreads();

#pragma unroll
        for (int kk = 0; kk < 32; kk++) {
            float4 a4 = *reinterpret_cast<const float4*>(&As[kk * AS_S + tr * 4]);
            float4 b4 = *reinterpret_cast<const float4*>(&Ws[(k0 + kk) * 64 + tc * 4]);
            unsigned long long a01, a23, bb0, bb1, bb2, bb3;
            asm("mov.b64 %0, {%1, %2};" : "=l"(a01) : "f"(a4.x), "f"(a4.y));
            asm("mov.b64 %0, {%1, %2};" : "=l"(a23) : "f"(a4.z), "f"(a4.w));
            asm("mov.b64 %0, {%1, %1};" : "=l"(bb0) : "f"(b4.x));
            asm("mov.b64 %0, {%1, %1};" : "=l"(bb1) : "f"(b4.y));
            asm("mov.b64 %0, {%1, %1};" : "=l"(bb2) : "f"(b4.z));
            asm("mov.b64 %0, {%1, %1};" : "=l"(bb3) : "f"(b4.w));
            asm("fma.rn.f32x2 %0, %1, %2, %0;" : "+l"(acc[0][0]) : "l"(a01), "l"(bb0));
            asm("fma.rn.f32x2 %0, %1, %2, %0;" : "+l"(acc[0][1]) : "l"(a01), "l"(bb1));
            asm("fma.rn.f32x2 %0, %1, %2, %0;" : "+l"(acc[0][2]) : "l"(a01), "l"(bb2));
            asm("fma.rn.f32x2 %0, %1, %2, %0;" : "+l"(acc[0][3]) : "l"(a01), "l"(bb3));
            asm("fma.rn.f32x2 %0, %1, %2, %0;" : "+l"(acc[1][0]) : "l"(a23), "l"(bb0));
            asm("fma.rn.f32x2 %0, %1, %2, %0;" : "+l"(acc[1][1]) : "l"(a23), "l"(bb1));
            asm("fma.rn.f32x2 %0, %1, %2, %0;" : "+l"(acc[1][2]) : "l"(a23), "l"(bb2));
            asm("fma.rn.f32x2 %0, %1, %2, %0;" : "+l"(acc[1][3]) : "l"(a23), "l"(bb3));
        }
    }

    // Epilogue: unpack, scale by ns[row], store.
#pragma unroll
    for (int rp = 0; rp < 2; rp++) {
        float lo[4], hi[4];
#pragma unroll
        for (int c = 0; c < 4; c++)
            asm("mov.b64 {%0, %1}, %2;" : "=f"(lo[c]), "=f"(hi[c]) : "l"(acc[rp][c]));
        int rlo = row0 + tr * 4 + rp * 2;
        int rhi = rlo + 1;
        if (rlo < M) {
            float s = g_ns[rlo];
#pragma unroll
            for (int c = 0; c < 4; c++) {
                int col = tc * 4 + c;
                if (col < N) g_bufA[(long long)rlo * N + col] = lo[c] * s;
            }
        }
        if (rhi < M) {
            float s = g_ns[rhi];
#pragma unroll
            for (int c = 0; c < 4; c++) {
                int col = tc * 4 + c;
                if (col < N) g_bufA[(long long)rhi * N + col] = hi[c] * s;
            }
        }
    }
}

// ---------------------------------------------------------------------------
// Fused SpMM-gather (from g_bufA via CSR) + nd + bias + [relu] + log_softmax.
// Warp per dst row. out = outp if non-null else g_bufB. No float atomics.
// ---------------------------------------------------------------------------
template<int F, bool RELU>
__global__ void spmm_fused_kernel(const float* __restrict__ bias, int n,
                                  float* __restrict__ outp) {
    constexpr int CH = F / 4;       // float4 chunks per row
    constexpr int G = 32 / CH;      // edge groups per warp

    int row = blockIdx.x * (blockDim.x >> 5) + (threadIdx.x >> 5);
    if (row >= n) return;
    int lane = threadIdx.x & 31;
    int g = lane / CH;
    int sub = lane - g * CH;

    int start = g_rowptr[row];
    int end = g_rowptr[row + 1];

    float4 acc = make_float4(0.f, 0.f, 0.f, 0.f);
    if (g < G) {
#pragma unroll 2
        for (int e = start + g; e < end; e += G) {
            int s = g_col[e];
            float4 v = *reinterpret_cast<const float4*>(&g_bufA[(long long)s * F + sub * 4]);
            acc.x += v.x; acc.y += v.y; acc.z += v.z; acc.w += v.w;
        }
    }

    float4 tot = acc;
#pragma unroll
    for (int k = 1; k < G; k++) {
        tot.x += __shfl_sync(0xffffffffu, acc.x, sub + k * CH);
        tot.y += __shfl_sync(0xffffffffu, acc.y, sub + k * CH);
        tot.z += __shfl_sync(0xffffffffu, acc.z, sub + k * CH);
        tot.w += __shfl_sync(0xffffffffu, acc.w, sub + k * CH);
    }

    float ndv = g_nd[row];
    float4 bv = *reinterpret_cast<const float4*>(bias + sub * 4);
    float4 x;
    x.x = tot.x * ndv + bv.x;
    x.y = tot.y * ndv + bv.y;
    x.z = tot.z * ndv + bv.z;
    x.w = tot.w * ndv + bv.w;
    if (RELU) {
        x.x = fmaxf(x.x, 0.f); x.y = fmaxf(x.y, 0.f);
        x.z = fmaxf(x.z, 0.f); x.w = fmaxf(x.w, 0.f);
    }

    bool valid = (lane < CH);
    float m = valid ? fmaxf(fmaxf(x.x, x.y), fmaxf(x.z, x.w)) : -FLT_MAX;
#pragma unroll
    for (int o = 8; o > 0; o >>= 1) m = fmaxf(m, __shfl_xor_sync(0xffffffffu, m, o));
    float s = valid ? (expf(x.x - m) + expf(x.y - m) + expf(x.z - m) + expf(x.w - m)) : 0.f;
#pragma unroll
    for (int o = 8; o > 0; o >>= 1) s += __shfl_xor_sync(0xffffffffu, s, o);
    float ls = m + logf(s);

    if (valid) {
        float* out = outp ? outp : g_bufB;
        float4 r;
        r.x = x.x - ls; r.y = x.y - ls; r.z = x.z - ls; r.w = x.w - ls;
        *reinterpret_cast<float4*>(out + (long long)row * F + sub * 4) = r;
    }
}

// ---------------------------------------------------------------------------
// Launch — kernel launches only.
// ---------------------------------------------------------------------------
extern "C" void kernel_launch(void* const* d_in, const int* in_sizes, int n_in,
                              void* d_out, int out_size) {
    const float* feats = (const float*)d_in[0];
    const int*   src   = (const int*)d_in[1];   // int32
    const int*   dst   = (const int*)d_in[2];   // int32
    const float* W0    = (const float*)d_in[3];
    const float* b0    = (const float*)d_in[4];
    const float* W1    = (const float*)d_in[5];
    const float* b1    = (const float*)d_in[6];
    const float* W2    = (const float*)d_in[7];
    const float* b2    = (const float*)d_in[8];

    int N = in_sizes[0] / 128;   // 100000
    int E = in_sizes[1];         // 1600000
    float* outp = (float*)d_out;

    int scan_blocks = (N + SCAN_TILE - 1) / SCAN_TILE;   // 98

    // ---- CSR build + norms ----
    zero_deg_kernel<<<(N + 255) / 256, 256>>>(N);
    deg_kernel<<<(E + 255) / 256, 256>>>(src, dst, E);
    norm_kernel<<<(N + 255) / 256, 256>>>(N);
    scan_reduce_kernel<<<scan_blocks, 256>>>(N);
    scan_blksums_kernel<<<1, 128>>>(scan_blocks, N);
    scan_write_kernel<<<scan_blocks, 256>>>(N);
    fill_kernel<<<(E + 255) / 256, 256>>>(src, dst, E);

    int spmm_blocks = (N + 7) / 8;
    int gemm_blocks = (N + 63) / 64;

    // ---- layer 0: 128 -> 64, relu, log_softmax ----
    gemm_ns_kernel<128, 64><<<gemm_blocks, 256>>>(feats, W0, N);
    spmm_fused_kernel<64, true><<<spmm_blocks, 256>>>(b0, N, nullptr);

    // ---- layer 1: 64 -> 64, relu, log_softmax ----
    gemm_ns_kernel<64, 64><<<gemm_blocks, 256>>>(nullptr, W1, N);
    spmm_fused_kernel<64, true><<<spmm_blocks, 256>>>(b1, N, nullptr);

    // ---- layer 2: 64 -> 40, no relu, log_softmax -> d_out ----
    gemm_ns_kernel<64, 40><<<gemm_blocks, 256>>>(nullptr, W2, N);
    spmm_fused_kernel<40, false><<<spmm_blocks, 256>>>(b2, N, outp);
}

// round 9
// speedup vs baseline: 1.6605x; 1.0279x over previous
#include <cuda_runtime.h>
#include <math.h>
#include <float.h>

#define MAX_NODES 100000
#define MAX_EDGES 1600000
#define SCAN_TILE 1024
#define MAX_SCAN_BLOCKS 128

// Scratch — referenced directly from device code.
__device__ __align__(16) float g_bufA[MAX_NODES * 64];
__device__ __align__(16) float g_bufB[MAX_NODES * 64];
__device__ int   g_deg_out[MAX_NODES];
__device__ __align__(16) int g_deg_in[MAX_NODES];
__device__ int   g_rowptr[MAX_NODES + 1];
__device__ int   g_cursor[MAX_NODES];
__device__ int   g_col[MAX_EDGES];
__device__ float g_ns[MAX_NODES];
__device__ float g_nd[MAX_NODES];
__device__ int   g_blksum[MAX_SCAN_BLOCKS];
__device__ int   g_blkoff[MAX_SCAN_BLOCKS];

// ---------------------------------------------------------------------------
__global__ void zero_deg_kernel(int n) {
    int i = blockIdx.x * blockDim.x + threadIdx.x;
    if (i < n) { g_deg_out[i] = 0; g_deg_in[i] = 0; }
}

__global__ void deg_kernel(const int* __restrict__ src,
                           const int* __restrict__ dst, int E) {
    int i = blockIdx.x * blockDim.x + threadIdx.x;
    if (i < E) {
        atomicAdd(&g_deg_out[src[i]], 1);
        atomicAdd(&g_deg_in[dst[i]], 1);
    }
}

__global__ void norm_kernel(int n) {
    int i = blockIdx.x * blockDim.x + threadIdx.x;
    if (i < n) {
        int a = g_deg_out[i];
        int b = g_deg_in[i];
        g_ns[i] = (a > 0) ? rsqrtf((float)a) : 0.0f;
        g_nd[i] = (b > 0) ? rsqrtf((float)b) : 0.0f;
    }
}

// ---------------------------------------------------------------------------
// Grid-wide exclusive scan of g_deg_in -> g_rowptr/g_cursor.
// ---------------------------------------------------------------------------
__device__ __forceinline__ int warp_incl_scan(int v, int lane) {
#pragma unroll
    for (int o = 1; o < 32; o <<= 1) {
        int t = __shfl_up_sync(0xffffffffu, v, o);
        if (lane >= o) v += t;
    }
    return v;
}

__global__ void scan_reduce_kernel(int n) {
    __shared__ int wsum[8];
    int tid = threadIdx.x, lane = tid & 31, wid = tid >> 5;
    int base = blockIdx.x * SCAN_TILE + tid * 4;
    int s = 0;
    if (base < n) {
        int4 v = *reinterpret_cast<const int4*>(&g_deg_in[base]);
        s = v.x + v.y + v.z + v.w;
    }
#pragma unroll
    for (int o = 16; o > 0; o >>= 1) s += __shfl_xor_sync(0xffffffffu, s, o);
    if (lane == 0) wsum[wid] = s;
    __syncthreads();
    if (tid == 0) {
        int t = 0;
#pragma unroll
        for (int w = 0; w < 8; w++) t += wsum[w];
        g_blksum[blockIdx.x] = t;
    }
}

__global__ void scan_blksums_kernel(int nb, int n) {
    __shared__ int woff[4];
    int tid = threadIdx.x, lane = tid & 31, wid = tid >> 5;  // 128 threads
    int v = (tid < nb) ? g_blksum[tid] : 0;
    int incl = warp_incl_scan(v, lane);
    if (lane == 31) woff[wid] = incl;
    __syncthreads();
    if (tid == 0) {
        int acc = 0;
#pragma unroll
        for (int w = 0; w < 4; w++) { int t = woff[w]; woff[w] = acc; acc += t; }
    }
    __syncthreads();
    int excl = incl - v + woff[wid];
    if (tid < nb) g_blkoff[tid] = excl;
    if (tid == nb - 1) g_rowptr[n] = excl + v;
}

__global__ void scan_write_kernel(int n) {
    __shared__ int woff[8];
    int tid = threadIdx.x, lane = tid & 31, wid = tid >> 5;  // 256 threads
    int base = blockIdx.x * SCAN_TILE + tid * 4;
    int4 v = make_int4(0, 0, 0, 0);
    if (base < n) v = *reinterpret_cast<const int4*>(&g_deg_in[base]);
    int s = v.x + v.y + v.z + v.w;
    int incl = warp_incl_scan(s, lane);
    if (lane == 31) woff[wid] = incl;
    __syncthreads();
    if (tid == 0) {
        int acc = 0;
#pragma unroll
        for (int w = 0; w < 8; w++) { int t = woff[w]; woff[w] = acc; acc += t; }
    }
    __syncthreads();
    if (base < n) {
        int excl = incl - s + woff[wid] + g_blkoff[blockIdx.x];
        int p0 = excl, p1 = p0 + v.x, p2 = p1 + v.y, p3 = p2 + v.z;
        *reinterpret_cast<int4*>(&g_rowptr[base]) = make_int4(p0, p1, p2, p3);
        *reinterpret_cast<int4*>(&g_cursor[base]) = make_int4(p0, p1, p2, p3);
    }
}

__global__ void fill_kernel(const int* __restrict__ src,
                            const int* __restrict__ dst, int E) {
    int e = blockIdx.x * blockDim.x + threadIdx.x;
    if (e < E) {
        int d = dst[e];
        int pos = atomicAdd(&g_cursor[d], 1);
        g_col[pos] = src[e];
    }
}

// ---------------------------------------------------------------------------
// GEMM (packed f32x2): g_bufA[M,N] = (X[M,K] @ W[K,N]) [* g_ns[row] if SCALE]
// ---------------------------------------------------------------------------
#define AS_S 68

template<int K, int N, bool SCALE_NS>
__global__ void gemm_ns_kernel(const float* __restrict__ Xext,
                               const float* __restrict__ W, int M) {
    __shared__ __align__(16) float Ws[K * 64];
    __shared__ __align__(16) float As[32 * AS_S];

    const float* X = Xext ? Xext : g_bufB;
    const int tid = threadIdx.x;
    const int tr = tid >> 4;
    const int tc = tid & 15;
    const int row0 = blockIdx.x * 64;

    for (int t = tid; t < K * 64; t += 256) {
        int k = t >> 6, c = t & 63;
        Ws[t] = (c < N) ? W[k * N + c] : 0.0f;
    }

    unsigned long long acc[2][4];
#pragma unroll
    for (int rp = 0; rp < 2; rp++)
#pragma unroll
        for (int c = 0; c < 4; c++) acc[rp][c] = 0ull;

    for (int k0 = 0; k0 < K; k0 += 32) {
        __syncthreads();
#pragma unroll
        for (int it = 0; it < 2; it++) {
            int idx = tid + it * 256;
            int row = idx >> 3;
            int kc = idx & 7;
            float4 v = make_float4(0.f, 0.f, 0.f, 0.f);
            if (row0 + row < M)
                v = *reinterpret_cast<const float4*>(&X[(long long)(row0 + row) * K + k0 + kc * 4]);
            As[(kc * 4 + 0) * AS_S + row] = v.x;
            As[(kc * 4 + 1) * AS_S + row] = v.y;
            As[(kc * 4 + 2) * AS_S + row] = v.z;
            As[(kc * 4 + 3) * AS_S + row] = v.w;
        }
        __syncthreads();

#pragma unroll
        for (int kk = 0; kk < 32; kk++) {
            float4 a4 = *reinterpret_cast<const float4*>(&As[kk * AS_S + tr * 4]);
            float4 b4 = *reinterpret_cast<const float4*>(&Ws[(k0 + kk) * 64 + tc * 4]);
            unsigned long long a01, a23, bb0, bb1, bb2, bb3;
            asm("mov.b64 %0, {%1, %2};" : "=l"(a01) : "f"(a4.x), "f"(a4.y));
            asm("mov.b64 %0, {%1, %2};" : "=l"(a23) : "f"(a4.z), "f"(a4.w));
            asm("mov.b64 %0, {%1, %1};" : "=l"(bb0) : "f"(b4.x));
            asm("mov.b64 %0, {%1, %1};" : "=l"(bb1) : "f"(b4.y));
            asm("mov.b64 %0, {%1, %1};" : "=l"(bb2) : "f"(b4.z));
            asm("mov.b64 %0, {%1, %1};" : "=l"(bb3) : "f"(b4.w));
            asm("fma.rn.f32x2 %0, %1, %2, %0;" : "+l"(acc[0][0]) : "l"(a01), "l"(bb0));
            asm("fma.rn.f32x2 %0, %1, %2, %0;" : "+l"(acc[0][1]) : "l"(a01), "l"(bb1));
            asm("fma.rn.f32x2 %0, %1, %2, %0;" : "+l"(acc[0][2]) : "l"(a01), "l"(bb2));
            asm("fma.rn.f32x2 %0, %1, %2, %0;" : "+l"(acc[0][3]) : "l"(a01), "l"(bb3));
            asm("fma.rn.f32x2 %0, %1, %2, %0;" : "+l"(acc[1][0]) : "l"(a23), "l"(bb0));
            asm("fma.rn.f32x2 %0, %1, %2, %0;" : "+l"(acc[1][1]) : "l"(a23), "l"(bb1));
            asm("fma.rn.f32x2 %0, %1, %2, %0;" : "+l"(acc[1][2]) : "l"(a23), "l"(bb2));
            asm("fma.rn.f32x2 %0, %1, %2, %0;" : "+l"(acc[1][3]) : "l"(a23), "l"(bb3));
        }
    }

#pragma unroll
    for (int rp = 0; rp < 2; rp++) {
        float lo[4], hi[4];
#pragma unroll
        for (int c = 0; c < 4; c++)
            asm("mov.b64 {%0, %1}, %2;" : "=f"(lo[c]), "=f"(hi[c]) : "l"(acc[rp][c]));
        int rlo = row0 + tr * 4 + rp * 2;
        int rhi = rlo + 1;
        if (rlo < M) {
            float s = SCALE_NS ? g_ns[rlo] : 1.0f;
#pragma unroll
            for (int c = 0; c < 4; c++) {
                int col = tc * 4 + c;
                if (col < N) g_bufA[(long long)rlo * N + col] = lo[c] * s;
            }
        }
        if (rhi < M) {
            float s = SCALE_NS ? g_ns[rhi] : 1.0f;
#pragma unroll
            for (int c = 0; c < 4; c++) {
                int col = tc * 4 + c;
                if (col < N) g_bufA[(long long)rhi * N + col] = hi[c] * s;
            }
        }
    }
}

// ---------------------------------------------------------------------------
// Fused SpMM-gather + nd + bias + [relu] + log_softmax. Warp per dst row.
// APPLY_NS: multiply each gathered row by g_ns[src] (layer 0 path, which lets
// GEMM0 run concurrently with the CSR/degree build).
// ---------------------------------------------------------------------------
template<int F, bool RELU, bool APPLY_NS>
__global__ void spmm_fused_kernel(const float* __restrict__ bias, int n,
                                  float* __restrict__ outp) {
    constexpr int CH = F / 4;
    constexpr int G = 32 / CH;

    int row = blockIdx.x * (blockDim.x >> 5) + (threadIdx.x >> 5);
    if (row >= n) return;
    int lane = threadIdx.x & 31;
    int g = lane / CH;
    int sub = lane - g * CH;

    int start = g_rowptr[row];
    int end = g_rowptr[row + 1];

    float4 acc = make_float4(0.f, 0.f, 0.f, 0.f);
    if (g < G) {
#pragma unroll 2
        for (int e = start + g; e < end; e += G) {
            int s = g_col[e];
            float w = APPLY_NS ? g_ns[s] : 1.0f;
            float4 v = *reinterpret_cast<const float4*>(&g_bufA[(long long)s * F + sub * 4]);
            if (APPLY_NS) {
                acc.x = fmaf(w, v.x, acc.x);
                acc.y = fmaf(w, v.y, acc.y);
                acc.z = fmaf(w, v.z, acc.z);
                acc.w = fmaf(w, v.w, acc.w);
            } else {
                acc.x += v.x; acc.y += v.y; acc.z += v.z; acc.w += v.w;
            }
        }
    }

    float4 tot = acc;
#pragma unroll
    for (int k = 1; k < G; k++) {
        tot.x += __shfl_sync(0xffffffffu, acc.x, sub + k * CH);
        tot.y += __shfl_sync(0xffffffffu, acc.y, sub + k * CH);
        tot.z += __shfl_sync(0xffffffffu, acc.z, sub + k * CH);
        tot.w += __shfl_sync(0xffffffffu, acc.w, sub + k * CH);
    }

    float ndv = g_nd[row];
    float4 bv = *reinterpret_cast<const float4*>(bias + sub * 4);
    float4 x;
    x.x = tot.x * ndv + bv.x;
    x.y = tot.y * ndv + bv.y;
    x.z = tot.z * ndv + bv.z;
    x.w = tot.w * ndv + bv.w;
    if (RELU) {
        x.x = fmaxf(x.x, 0.f); x.y = fmaxf(x.y, 0.f);
        x.z = fmaxf(x.z, 0.f); x.w = fmaxf(x.w, 0.f);
    }

    bool valid = (lane < CH);
    float m = valid ? fmaxf(fmaxf(x.x, x.y), fmaxf(x.z, x.w)) : -FLT_MAX;
#pragma unroll
    for (int o = 8; o > 0; o >>= 1) m = fmaxf(m, __shfl_xor_sync(0xffffffffu, m, o));
    float s = valid ? (expf(x.x - m) + expf(x.y - m) + expf(x.z - m) + expf(x.w - m)) : 0.f;
#pragma unroll
    for (int o = 8; o > 0; o >>= 1) s += __shfl_xor_sync(0xffffffffu, s, o);
    float ls = m + logf(s);

    if (valid) {
        float* out = outp ? outp : g_bufB;
        float4 r;
        r.x = x.x - ls; r.y = x.y - ls; r.z = x.z - ls; r.w = x.w - ls;
        *reinterpret_cast<float4*>(out + (long long)row * F + sub * 4) = r;
    }
}

// ---------------------------------------------------------------------------
// Launch. CSR build forked onto a side stream (event fork/join is capture-
// legal); GEMM0 (no ns dependency) overlaps it on the main stream.
// ---------------------------------------------------------------------------
extern "C" void kernel_launch(void* const* d_in, const int* in_sizes, int n_in,
                              void* d_out, int out_size) {
    const float* feats = (const float*)d_in[0];
    const int*   src   = (const int*)d_in[1];
    const int*   dst   = (const int*)d_in[2];
    const float* W0    = (const float*)d_in[3];
    const float* b0    = (const float*)d_in[4];
    const float* W1    = (const float*)d_in[5];
    const float* b1    = (const float*)d_in[6];
    const float* W2    = (const float*)d_in[7];
    const float* b2    = (const float*)d_in[8];

    int N = in_sizes[0] / 128;   // 100000
    int E = in_sizes[1];         // 1600000
    float* outp = (float*)d_out;

    // Created once, on the first (non-capture) correctness call.
    static cudaStream_t s1 = nullptr;
    static cudaEvent_t evFork = nullptr, evJoin = nullptr;
    if (s1 == nullptr) {
        cudaStreamCreateWithFlags(&s1, cudaStreamNonBlocking);
        cudaEventCreateWithFlags(&evFork, cudaEventDisableTiming);
        cudaEventCreateWithFlags(&evJoin, cudaEventDisableTiming);
    }

    int scan_blocks = (N + SCAN_TILE - 1) / SCAN_TILE;   // 98
    int spmm_blocks = (N + 7) / 8;
    int gemm_blocks = (N + 63) / 64;

    // ---- fork: CSR build + norms on side stream ----
    cudaEventRecord(evFork, 0);
    cudaStreamWaitEvent(s1, evFork, 0);
    zero_deg_kernel<<<(N + 255) / 256, 256, 0, s1>>>(N);
    deg_kernel<<<(E + 255) / 256, 256, 0, s1>>>(src, dst, E);
    norm_kernel<<<(N + 255) / 256, 256, 0, s1>>>(N);
    scan_reduce_kernel<<<scan_blocks, 256, 0, s1>>>(N);
    scan_blksums_kernel<<<1, 128, 0, s1>>>(scan_blocks, N);
    scan_write_kernel<<<scan_blocks, 256, 0, s1>>>(N);
    fill_kernel<<<(E + 255) / 256, 256, 0, s1>>>(src, dst, E);
    cudaEventRecord(evJoin, s1);

    // ---- concurrently: layer-0 GEMM (no ns) on main stream ----
    gemm_ns_kernel<128, 64, false><<<gemm_blocks, 256>>>(feats, W0, N);

    // ---- join, then layer-0 gather applies ns per edge ----
    cudaStreamWaitEvent(0, evJoin, 0);
    spmm_fused_kernel<64, true, true><<<spmm_blocks, 256>>>(b0, N, nullptr);

    // ---- layer 1 ----
    gemm_ns_kernel<64, 64, true><<<gemm_blocks, 256>>>(nullptr, W1, N);
    spmm_fused_kernel<64, true, false><<<spmm_blocks, 256>>>(b1, N, nullptr);

    // ---- layer 2 ----
    gemm_ns_kernel<64, 40, true><<<gemm_blocks, 256>>>(nullptr, W2, N);
    spmm_fused_kernel<40, false, false><<<spmm_blocks, 256>>>(b2, N, outp);
}